// round 11
// baseline (speedup 1.0000x reference)
#include <cuda_runtime.h>
#include <cstdint>

// LogicLayer: out[i,j] = g_a(x[i,idx_a[j]]) * g_b(x[i,idx_b[j]])
//   g(v) = (logit > 0) ? 1-v : v
//
// R11 vs R10 (best = R8: 60.1us = 53.8 main + ~6 prep/gaps):
//  - SINGLE kernel. Each thread packs its own 32 (flag,idx) words into
//    8 x uint4 registers ONCE (during the first TMA fill's shadow) and
//    reuses them for all ~7 rows:
//      * prep kernel + launch gap gone (total == main)
//      * per-row 128KiB g_packed re-read gone (-1024 L1 wf/row)
//  - float4 output granularity: 8 iters x STG.128.cs
//  - fp32 row in smem (u16 experiment regressed), persistent 148 CTAs,
//    whole-row TMA fill + next-row L2 prefetch.

#define IN_DIM   32768
#define OUT_DIM  32768
#define BATCH    1024
#define NTHREADS 1024
#define NSM      148
#define ITERS4   (OUT_DIM / (NTHREADS * 4))   // 8

__device__ __forceinline__ uint32_t smem_u32(const void* p) {
    uint32_t a;
    asm("{ .reg .u64 t; cvta.to.shared.u64 t, %1; cvt.u32.u64 %0, t; }"
        : "=r"(a) : "l"(p));
    return a;
}

__device__ __forceinline__ void stg_cs_v4(float* p, float v0, float v1,
                                          float v2, float v3) {
    asm volatile("st.global.cs.v4.f32 [%0], {%1, %2, %3, %4};"
                 :: "l"(p), "f"(v0), "f"(v1), "f"(v2), "f"(v3) : "memory");
}

__device__ __forceinline__ void mbar_wait(uint32_t mbar_a, uint32_t phase) {
    uint32_t done;
    asm volatile(
        "{\n\t.reg .pred P;\n\t"
        "mbarrier.try_wait.parity.acquire.cta.shared::cta.b64 P, [%1], %2, 0x989680;\n\t"
        "selp.b32 %0, 1, 0, P;\n\t}"
        : "=r"(done) : "r"(mbar_a), "r"(phase) : "memory");
    if (!done) {
        asm volatile(
            "{\n\t.reg .pred P;\n"
            "WL_%=:\n\t"
            "mbarrier.try_wait.parity.acquire.cta.shared::cta.b64 P, [%0], %1, 0x989680;\n\t"
            "@P bra.uni WD_%=;\n\t"
            "bra.uni WL_%=;\n"
            "WD_%=:\n\t}"
            :: "r"(mbar_a), "r"(phase) : "memory");
    }
}

__device__ __forceinline__ uint32_t pack_one(int ia, int ib, float la, float lb) {
    uint32_t fa = (la > 0.0f) ? 1u : 0u;
    uint32_t fb = (lb > 0.0f) ? 1u : 0u;
    return (fa << 31) | (((uint32_t)ia & 0x7FFFu) << 16)
         | (fb << 15) | ((uint32_t)ib & 0x7FFFu);
}

__device__ __forceinline__ float gate2(uint32_t p, const float* sx) {
    float a = sx[(p >> 16) & 0x7FFFu];
    float b = sx[p & 0x7FFFu];
    if (p & 0x80000000u) a = 1.0f - a;
    if (p & 0x00008000u) b = 1.0f - b;
    return a * b;
}

__global__ __launch_bounds__(NTHREADS, 1)
void logic_layer_kernel(const float* __restrict__ x,
                        const float* __restrict__ logits,
                        const int* __restrict__ idx_a,
                        const int* __restrict__ idx_b,
                        float* __restrict__ out) {
    extern __shared__ float sx[];
    __shared__ __align__(8) uint64_t mbar;

    const int t = threadIdx.x;
    const uint32_t mbar_a = smem_u32(&mbar);
    const uint32_t dst_a  = smem_u32(sx);

    if (t == 0) {
        asm volatile("mbarrier.init.shared.b64 [%0], 1;" :: "r"(mbar_a) : "memory");
        asm volatile("fence.proxy.async.shared::cta;" ::: "memory");
    }
    __syncthreads();

    // Kick the first row's fill immediately; packing hides in its shadow.
    if (t == 0) {
        asm volatile("mbarrier.arrive.expect_tx.shared.b64 _, [%0], %1;"
                     :: "r"(mbar_a), "r"((uint32_t)(IN_DIM * 4)) : "memory");
        asm volatile("cp.async.bulk.shared::cta.global.mbarrier::complete_tx::bytes "
                     "[%0], [%1], %2, [%3];"
                     :: "r"(dst_a), "l"(x + (size_t)blockIdx.x * IN_DIM),
                        "r"((uint32_t)(IN_DIM * 4)), "r"(mbar_a)
                     : "memory");
    }

    // ---- one-time: pack this thread's 32 j's into 8 x uint4 registers ----
    // thread t handles j = k*4096 + 4t + {0,1,2,3}, k = 0..7
    uint4 pk[ITERS4];
    {
        const int4*   ia4 = reinterpret_cast<const int4*>(idx_a);
        const int4*   ib4 = reinterpret_cast<const int4*>(idx_b);
        const float4* lg4 = reinterpret_cast<const float4*>(logits);
        #pragma unroll
        for (int k = 0; k < ITERS4; k++) {
            int g = k * NTHREADS + t;          // float4-granule index
            int4 ia = ia4[g];
            int4 ib = ib4[g];
            float4 l0 = lg4[2 * g];            // logits for j0, j1
            float4 l1 = lg4[2 * g + 1];        // logits for j2, j3
            pk[k].x = pack_one(ia.x, ib.x, l0.x, l0.y);
            pk[k].y = pack_one(ia.y, ib.y, l0.z, l0.w);
            pk[k].z = pack_one(ia.z, ib.z, l1.x, l1.y);
            pk[k].w = pack_one(ia.w, ib.w, l1.z, l1.w);
        }
    }

    uint32_t phase = 0;

    for (int row = blockIdx.x; row < BATCH; row += NSM) {
        const int nrow = row + NSM;

        // Pull this CTA's next row toward L2 while we work on this one.
        if (t == 32 && nrow < BATCH) {
            asm volatile("cp.async.bulk.prefetch.L2.global [%0], %1;"
                         :: "l"(x + (size_t)nrow * IN_DIM),
                            "r"((uint32_t)(IN_DIM * 4)) : "memory");
        }

        mbar_wait(mbar_a, phase);
        phase ^= 1;

        float* orow = out + (size_t)row * OUT_DIM;

        #pragma unroll
        for (int k = 0; k < ITERS4; k++) {
            uint4 p = pk[k];
            float r0 = gate2(p.x, sx);
            float r1 = gate2(p.y, sx);
            float r2 = gate2(p.z, sx);
            float r3 = gate2(p.w, sx);
            stg_cs_v4(&orow[(size_t)k * NTHREADS * 4 + t * 4], r0, r1, r2, r3);
        }

        __syncthreads();  // all gathers of this row done reading sx

        // Refill for this CTA's next row.
        if (t == 0 && nrow < BATCH) {
            asm volatile("mbarrier.arrive.expect_tx.shared.b64 _, [%0], %1;"
                         :: "r"(mbar_a), "r"((uint32_t)(IN_DIM * 4)) : "memory");
            asm volatile("cp.async.bulk.shared::cta.global.mbarrier::complete_tx::bytes "
                         "[%0], [%1], %2, [%3];"
                         :: "r"(dst_a), "l"(x + (size_t)nrow * IN_DIM),
                            "r"((uint32_t)(IN_DIM * 4)), "r"(mbar_a)
                     : "memory");
        }
    }
}

extern "C" void kernel_launch(void* const* d_in, const int* in_sizes, int n_in,
                              void* d_out, int out_size) {
    const float* x      = (const float*)d_in[0];
    const float* logits = (const float*)d_in[1];
    const int*   idx_a  = (const int*)d_in[2];
    const int*   idx_b  = (const int*)d_in[3];
    float* out = (float*)d_out;

    cudaFuncSetAttribute(logic_layer_kernel,
                         cudaFuncAttributeMaxDynamicSharedMemorySize,
                         IN_DIM * (int)sizeof(float));

    logic_layer_kernel<<<NSM, NTHREADS, IN_DIM * sizeof(float)>>>(
        x, logits, idx_a, idx_b, out);
}

// round 12
// speedup vs baseline: 2.1581x; 2.1581x over previous
#include <cuda_runtime.h>
#include <cstdint>

// LogicLayer: out[i,j] = g_a(x[i,idx_a[j]]) * g_b(x[i,idx_b[j]])
//   g(v) = (logit > 0) ? 1-v : v
//
// R12 vs R11 (133us reg-spill disaster; best = R8 60.1us, fp32 row, 32 warps/SM):
//  - u16 fixed-point row (x*65535) in 64KB smem -> 2 CTAs x 1024 thr/SM
//    (96% occ drives the L1 port; negation = XOR 0xFFFF, exact; quant
//    err ~1e-5, verified R10).
//  - conversion = direct LDG.128.cs -> cvt -> STS.64 (NO TMA/staging/
//    mbarriers — R10's pipeline overhead is what lost). 2 syncs/row.
//  - gate = 2 LDS.U16 + XOR + u32 IMAD + CVT + FMUL (cheaper than fp32 path).
//  - g_packed prep kernel, uint4 reloads per row (L2-resident), v4 .cs stores,
//    next-row L2 prefetch.

#define IN_DIM   32768
#define OUT_DIM  32768
#define BATCH    1024
#define NTHREADS 1024
#define GRID     296                          // 2 CTAs per SM
#define ITERS4   (OUT_DIM / (NTHREADS * 4))   // 8

__device__ uint32_t g_packed[OUT_DIM];

// ---------------- prep: pack (fa|ia | fb|ib) into one u32 per j --------------
__global__ __launch_bounds__(256)
void prep_kernel(const float* __restrict__ logits,
                 const int* __restrict__ idx_a,
                 const int* __restrict__ idx_b) {
    int j = blockIdx.x * 256 + threadIdx.x;
    uint32_t ia = (uint32_t)idx_a[j] & 0x7FFFu;
    uint32_t ib = (uint32_t)idx_b[j] & 0x7FFFu;
    uint32_t fa = (logits[2 * j]     > 0.0f) ? 1u : 0u;
    uint32_t fb = (logits[2 * j + 1] > 0.0f) ? 1u : 0u;
    g_packed[j] = (fa << 31) | (ia << 16) | (fb << 15) | ib;
}

// ---------------- helpers ----------------------------------------------------
__device__ __forceinline__ void stg_cs_v4(float* p, float v0, float v1,
                                          float v2, float v3) {
    asm volatile("st.global.cs.v4.f32 [%0], {%1, %2, %3, %4};"
                 :: "l"(p), "f"(v0), "f"(v1), "f"(v2), "f"(v3) : "memory");
}

__device__ __forceinline__ float gate_u16(uint32_t p, const uint16_t* sxu) {
    uint32_t ua = sxu[(p >> 16) & 0x7FFFu];
    uint32_t ub = sxu[p & 0x7FFFu];
    if (p & 0x80000000u) ua ^= 0xFFFFu;       // 1-a exactly in fixed point
    if (p & 0x00008000u) ub ^= 0xFFFFu;
    const float sc2 = 1.0f / (65535.0f * 65535.0f);
    return __uint2float_rn(ua * ub) * sc2;
}

// ---------------- main: persistent, 2 CTAs/SM, u16 row -----------------------
__global__ __launch_bounds__(NTHREADS, 2)
void logic_layer_kernel(const float* __restrict__ x,
                        float* __restrict__ out) {
    extern __shared__ uint16_t sxu[];          // 64 KB row buffer

    const int t = threadIdx.x;
    const uint4* packed4 = reinterpret_cast<const uint4*>(g_packed);
    uint2* sxu2 = reinterpret_cast<uint2*>(sxu);

    for (int row = blockIdx.x; row < BATCH; row += GRID) {
        const int nrow = row + GRID;

        // Pull this CTA's next row toward L2 while we work on this one.
        if (t == 0 && nrow < BATCH) {
            asm volatile("cp.async.bulk.prefetch.L2.global [%0], %1;"
                         :: "l"(x + (size_t)nrow * IN_DIM),
                            "r"((uint32_t)(IN_DIM * 4)) : "memory");
        }

        // ---- conversion: LDG.128.cs -> u16 pack -> STS.64 ----
        const float4* xr4 = reinterpret_cast<const float4*>(x + (size_t)row * IN_DIM);
        #pragma unroll
        for (int k = 0; k < 8; k++) {
            float4 v = __ldcs(&xr4[k * NTHREADS + t]);
            uint2 u;
            u.x = __float2uint_rn(v.x * 65535.0f)
                | (__float2uint_rn(v.y * 65535.0f) << 16);
            u.y = __float2uint_rn(v.z * 65535.0f)
                | (__float2uint_rn(v.w * 65535.0f) << 16);
            sxu2[k * NTHREADS + t] = u;
        }
        __syncthreads();

        // ---- gather phase ----
        float* orow = out + (size_t)row * OUT_DIM;
        #pragma unroll
        for (int k = 0; k < ITERS4; k++) {
            uint4 p = packed4[k * NTHREADS + t];
            float r0 = gate_u16(p.x, sxu);
            float r1 = gate_u16(p.y, sxu);
            float r2 = gate_u16(p.z, sxu);
            float r3 = gate_u16(p.w, sxu);
            stg_cs_v4(&orow[(size_t)(k * NTHREADS + t) * 4], r0, r1, r2, r3);
        }
        __syncthreads();   // row buffer free for next row's conversion
    }
}

extern "C" void kernel_launch(void* const* d_in, const int* in_sizes, int n_in,
                              void* d_out, int out_size) {
    const float* x      = (const float*)d_in[0];
    const float* logits = (const float*)d_in[1];
    const int*   idx_a  = (const int*)d_in[2];
    const int*   idx_b  = (const int*)d_in[3];
    float* out = (float*)d_out;

    cudaFuncSetAttribute(logic_layer_kernel,
                         cudaFuncAttributeMaxDynamicSharedMemorySize,
                         IN_DIM * (int)sizeof(uint16_t));

    prep_kernel<<<OUT_DIM / 256, 256>>>(logits, idx_a, idx_b);
    logic_layer_kernel<<<GRID, NTHREADS, IN_DIM * sizeof(uint16_t)>>>(x, out);
}

// round 13
// speedup vs baseline: 2.4857x; 1.1518x over previous
#include <cuda_runtime.h>
#include <cstdint>

// LogicLayer: out[i,j] = g_a(x[i,idx_a[j]]) * g_b(x[i,idx_b[j]])
//   g(v) = (logit > 0) ? 1-v : v
//
// R13: TWO rows per gather. smem holds a row PAIR as u32 per element:
//   lo16 = round(x[2p, i]*65535), hi16 = round(x[2p+1, i]*65535).
//   One LDS.32 feeds both rows' gates; negation for both rows is a single
//   XOR 0xFFFFFFFF (exact in fixed point); packed gate words are loaded
//   once per PAIR. Per-row L1 wavefronts drop ~9.9k -> ~6.5k vs best (R8).
//   1 CTA/SM (128KB smem), persistent over 512 pairs, next-pair L2 prefetch.
//   Quantization rel_err ~1.1e-5 (validated in R10/R12), threshold 1e-3.

#define IN_DIM   32768
#define OUT_DIM  32768
#define BATCH    1024
#define NPAIRS   (BATCH / 2)                  // 512
#define NTHREADS 1024
#define NSM      148
#define ITERS4   (OUT_DIM / (NTHREADS * 4))   // 8

__device__ uint32_t g_packed[OUT_DIM];

// ---------------- prep: pack (fa|ia | fb|ib) into one u32 per j --------------
__global__ __launch_bounds__(256)
void prep_kernel(const float* __restrict__ logits,
                 const int* __restrict__ idx_a,
                 const int* __restrict__ idx_b) {
    int j = blockIdx.x * 256 + threadIdx.x;
    uint32_t ia = (uint32_t)idx_a[j] & 0x7FFFu;
    uint32_t ib = (uint32_t)idx_b[j] & 0x7FFFu;
    uint32_t fa = (logits[2 * j]     > 0.0f) ? 1u : 0u;
    uint32_t fb = (logits[2 * j + 1] > 0.0f) ? 1u : 0u;
    g_packed[j] = (fa << 31) | (ia << 16) | (fb << 15) | ib;
}

// ---------------- helpers ----------------------------------------------------
__device__ __forceinline__ void stg_cs_v4(float* p, float v0, float v1,
                                          float v2, float v3) {
    asm volatile("st.global.cs.v4.f32 [%0], {%1, %2, %3, %4};"
                 :: "l"(p), "f"(v0), "f"(v1), "f"(v2), "f"(v3) : "memory");
}

// one gate, both rows: wa/wb are (row1<<16)|row0 fixed-point values
__device__ __forceinline__ void gate_pair(uint32_t p, const uint32_t* spk,
                                          float& r0, float& r1) {
    uint32_t wa = spk[(p >> 16) & 0x7FFFu];
    uint32_t wb = spk[p & 0x7FFFu];
    if (p & 0x80000000u) wa ^= 0xFFFFFFFFu;   // 1-a for BOTH rows, exact
    if (p & 0x00008000u) wb ^= 0xFFFFFFFFu;
    uint32_t lo = (wa & 0xFFFFu) * (wb & 0xFFFFu);
    uint32_t hi = (wa >> 16) * (wb >> 16);
    const float sc2 = 1.0f / (65535.0f * 65535.0f);
    r0 = __uint2float_rn(lo) * sc2;
    r1 = __uint2float_rn(hi) * sc2;
}

__device__ __forceinline__ uint32_t q16(float v) {
    return __float2uint_rn(v * 65535.0f);
}

// ---------------- main: persistent, row-pair in smem as u32 ------------------
__global__ __launch_bounds__(NTHREADS, 1)
void logic_layer_kernel(const float* __restrict__ x,
                        float* __restrict__ out) {
    extern __shared__ uint32_t spk[];          // 32768 x u32 = 128KB
    const int t = threadIdx.x;
    const uint4* packed4 = reinterpret_cast<const uint4*>(g_packed);

    for (int pr = blockIdx.x; pr < NPAIRS; pr += NSM) {
        const int row0 = 2 * pr;
        const int npr = pr + NSM;

        // Pull next pair (256KB contiguous) toward L2 while we work.
        if (t == 0 && npr < NPAIRS) {
            const float* nx = x + (size_t)(2 * npr) * IN_DIM;
            asm volatile("cp.async.bulk.prefetch.L2.global [%0], %1;"
                         :: "l"(nx), "r"((uint32_t)(IN_DIM * 4)) : "memory");
        }
        if (t == 32 && npr < NPAIRS) {
            const float* nx = x + (size_t)(2 * npr + 1) * IN_DIM;
            asm volatile("cp.async.bulk.prefetch.L2.global [%0], %1;"
                         :: "l"(nx), "r"((uint32_t)(IN_DIM * 4)) : "memory");
        }

        // ---- conversion: both rows -> packed u16x2 in smem ----
        const float4* r0p = reinterpret_cast<const float4*>(x + (size_t)row0 * IN_DIM);
        const float4* r1p = reinterpret_cast<const float4*>(x + (size_t)(row0 + 1) * IN_DIM);
        #pragma unroll
        for (int k = 0; k < 8; k++) {
            int g = k * NTHREADS + t;
            float4 a = __ldcs(&r0p[g]);
            float4 b = __ldcs(&r1p[g]);
            uint4 w;
            w.x = q16(a.x) | (q16(b.x) << 16);
            w.y = q16(a.y) | (q16(b.y) << 16);
            w.z = q16(a.z) | (q16(b.z) << 16);
            w.w = q16(a.w) | (q16(b.w) << 16);
            reinterpret_cast<uint4*>(spk)[g] = w;
        }
        __syncthreads();

        // ---- gather phase: 4 gates x 2 rows per iteration ----
        float* o0 = out + (size_t)row0 * OUT_DIM;
        float* o1 = o0 + OUT_DIM;
        #pragma unroll
        for (int k = 0; k < ITERS4; k++) {
            uint4 p = packed4[k * NTHREADS + t];
            float a0, a1, b0, b1, c0, c1, d0, d1;
            gate_pair(p.x, spk, a0, a1);
            gate_pair(p.y, spk, b0, b1);
            gate_pair(p.z, spk, c0, c1);
            gate_pair(p.w, spk, d0, d1);
            size_t off = (size_t)(k * NTHREADS + t) * 4;
            stg_cs_v4(&o0[off], a0, b0, c0, d0);
            stg_cs_v4(&o1[off], a1, b1, c1, d1);
        }
        __syncthreads();   // smem free for next pair's conversion
    }
}

extern "C" void kernel_launch(void* const* d_in, const int* in_sizes, int n_in,
                              void* d_out, int out_size) {
    const float* x      = (const float*)d_in[0];
    const float* logits = (const float*)d_in[1];
    const int*   idx_a  = (const int*)d_in[2];
    const int*   idx_b  = (const int*)d_in[3];
    float* out = (float*)d_out;

    cudaFuncSetAttribute(logic_layer_kernel,
                         cudaFuncAttributeMaxDynamicSharedMemorySize,
                         IN_DIM * (int)sizeof(uint32_t));

    prep_kernel<<<OUT_DIM / 256, 256>>>(logits, idx_a, idx_b);
    logic_layer_kernel<<<NSM, NTHREADS, IN_DIM * sizeof(uint32_t)>>>(x, out);
}

// round 14
// speedup vs baseline: 2.5263x; 1.0163x over previous
#include <cuda_runtime.h>
#include <cstdint>

// LogicLayer: out[i,j] = g_a(x[i,idx_a[j]]) * g_b(x[i,idx_b[j]])
//   g(v) = (logit > 0) ? 1-v : v
//
// R14 vs R13 (53.8us total / 50.4 main; L1 47%, issue 33% -> latency-bound,
// lockstep convoy on the per-iteration dependent packed-LDG):
//  - 2-deep register ring for the packed gate words: iter k uses the uint4
//    loaded at iter k-2; ring primed before the conversion barrier so the
//    first loads are in flight across the sync. Breaks the convoy.
//  - branch-free negation via sign-extension masks (frees regs/issue).
//  - everything else identical to R13 (row-pair u16x2 in 128KB smem,
//    one LDS.32 feeds both rows, persistent 148 CTAs, L2 prefetch,
//    v4 streaming stores). Quant rel_err ~1.1e-5.

#define IN_DIM   32768
#define OUT_DIM  32768
#define BATCH    1024
#define NPAIRS   (BATCH / 2)                  // 512
#define NTHREADS 1024
#define NSM      148
#define ITERS4   (OUT_DIM / (NTHREADS * 4))   // 8

__device__ uint32_t g_packed[OUT_DIM];

// ---------------- prep: pack (fa|ia | fb|ib) into one u32 per j --------------
__global__ __launch_bounds__(256)
void prep_kernel(const float* __restrict__ logits,
                 const int* __restrict__ idx_a,
                 const int* __restrict__ idx_b) {
    int j = blockIdx.x * 256 + threadIdx.x;
    uint32_t ia = (uint32_t)idx_a[j] & 0x7FFFu;
    uint32_t ib = (uint32_t)idx_b[j] & 0x7FFFu;
    uint32_t fa = (logits[2 * j]     > 0.0f) ? 1u : 0u;
    uint32_t fb = (logits[2 * j + 1] > 0.0f) ? 1u : 0u;
    g_packed[j] = (fa << 31) | (ia << 16) | (fb << 15) | ib;
}

// ---------------- helpers ----------------------------------------------------
__device__ __forceinline__ void stg_cs_v4(float* p, float v0, float v1,
                                          float v2, float v3) {
    asm volatile("st.global.cs.v4.f32 [%0], {%1, %2, %3, %4};"
                 :: "l"(p), "f"(v0), "f"(v1), "f"(v2), "f"(v3) : "memory");
}

// one gate, both rows; branch-free negation masks from packed-word bits
__device__ __forceinline__ void gate_pair(uint32_t p, const uint32_t* spk,
                                          float& r0, float& r1) {
    uint32_t wa = spk[(p >> 16) & 0x7FFFu];
    uint32_t wb = spk[p & 0x7FFFu];
    wa ^= (uint32_t)((int32_t)p >> 31);            // bit31 -> 0 / 0xFFFFFFFF
    wb ^= (uint32_t)((int32_t)(p << 16) >> 31);    // bit15 -> 0 / 0xFFFFFFFF
    uint32_t lo = (wa & 0xFFFFu) * (wb & 0xFFFFu);
    uint32_t hi = (wa >> 16) * (wb >> 16);
    const float sc2 = 1.0f / (65535.0f * 65535.0f);
    r0 = __uint2float_rn(lo) * sc2;
    r1 = __uint2float_rn(hi) * sc2;
}

__device__ __forceinline__ uint32_t q16(float v) {
    return __float2uint_rn(v * 65535.0f);
}

// ---------------- main: persistent, row-pair in smem as u32 ------------------
__global__ __launch_bounds__(NTHREADS, 1)
void logic_layer_kernel(const float* __restrict__ x,
                        float* __restrict__ out) {
    extern __shared__ uint32_t spk[];          // 32768 x u32 = 128KB
    const int t = threadIdx.x;
    const uint4* packed4 = reinterpret_cast<const uint4*>(g_packed);

    for (int pr = blockIdx.x; pr < NPAIRS; pr += NSM) {
        const int row0 = 2 * pr;
        const int npr = pr + NSM;

        // Pull next pair (2 rows) toward L2 while we work.
        if (t == 0 && npr < NPAIRS) {
            asm volatile("cp.async.bulk.prefetch.L2.global [%0], %1;"
                         :: "l"(x + (size_t)(2 * npr) * IN_DIM),
                            "r"((uint32_t)(IN_DIM * 4)) : "memory");
        }
        if (t == 32 && npr < NPAIRS) {
            asm volatile("cp.async.bulk.prefetch.L2.global [%0], %1;"
                         :: "l"(x + (size_t)(2 * npr + 1) * IN_DIM),
                            "r"((uint32_t)(IN_DIM * 4)) : "memory");
        }

        // ---- conversion: both rows -> packed u16x2 in smem ----
        const float4* r0p = reinterpret_cast<const float4*>(x + (size_t)row0 * IN_DIM);
        const float4* r1p = reinterpret_cast<const float4*>(x + (size_t)(row0 + 1) * IN_DIM);
        #pragma unroll
        for (int k = 0; k < 8; k++) {
            int g = k * NTHREADS + t;
            float4 a = __ldcs(&r0p[g]);
            float4 b = __ldcs(&r1p[g]);
            uint4 w;
            w.x = q16(a.x) | (q16(b.x) << 16);
            w.y = q16(a.y) | (q16(b.y) << 16);
            w.z = q16(a.z) | (q16(b.z) << 16);
            w.w = q16(a.w) | (q16(b.w) << 16);
            reinterpret_cast<uint4*>(spk)[g] = w;
        }

        // Prime the 2-deep packed ring BEFORE the barrier (loads fly over it).
        uint4 pr0 = packed4[0 * NTHREADS + t];
        uint4 pr1 = packed4[1 * NTHREADS + t];

        __syncthreads();

        // ---- gather phase: 4 gates x 2 rows per iteration, ring depth 2 ----
        float* o0 = out + (size_t)row0 * OUT_DIM;
        float* o1 = o0 + OUT_DIM;
        #pragma unroll
        for (int k = 0; k < ITERS4; k++) {
            uint4 p = (k & 1) ? pr1 : pr0;
            if (k + 2 < ITERS4) {
                uint4 nx = packed4[(k + 2) * NTHREADS + t];
                if (k & 1) pr1 = nx; else pr0 = nx;
            }
            float a0, a1, b0, b1, c0, c1, d0, d1;
            gate_pair(p.x, spk, a0, a1);
            gate_pair(p.y, spk, b0, b1);
            gate_pair(p.z, spk, c0, c1);
            gate_pair(p.w, spk, d0, d1);
            size_t off = (size_t)(k * NTHREADS + t) * 4;
            stg_cs_v4(&o0[off], a0, b0, c0, d0);
            stg_cs_v4(&o1[off], a1, b1, c1, d1);
        }
        __syncthreads();   // smem free for next pair's conversion
    }
}

extern "C" void kernel_launch(void* const* d_in, const int* in_sizes, int n_in,
                              void* d_out, int out_size) {
    const float* x      = (const float*)d_in[0];
    const float* logits = (const float*)d_in[1];
    const int*   idx_a  = (const int*)d_in[2];
    const int*   idx_b  = (const int*)d_in[3];
    float* out = (float*)d_out;

    cudaFuncSetAttribute(logic_layer_kernel,
                         cudaFuncAttributeMaxDynamicSharedMemorySize,
                         IN_DIM * (int)sizeof(uint32_t));

    prep_kernel<<<OUT_DIM / 256, 256>>>(logits, idx_a, idx_b);
    logic_layer_kernel<<<NSM, NTHREADS, IN_DIM * sizeof(uint32_t)>>>(x, out);
}